// round 13
// baseline (speedup 1.0000x reference)
#include <cuda_runtime.h>

// preds: [16,8,17,128,128] f32  -> flattened N=128, K=17, H=W=128
// gt:    [16,8,10,17,2]   f32  -> N=128, P=10, K=17, (x,y)
// out:   2 floats: total_within, total_across
//
// 64 blocks x 32 threads, TWO n per warp: lanes 0-9 own persons of n0,
// lanes 16-25 own persons of n1. No smem, no __syncthreads. Cross-block
// protocol: one packed u64 atomicAdd per block (count+=2 | within_q16 |
// across_q18); the block seeing prev count == 126 writes out.

#define N_FLAT 128
#define P_NUM 10
#define K_NUM 17
#define HW 128

#define Q_WITHIN 65536.0f    // 2^16
#define Q_ACROSS 262144.0f   // 2^18
#define SH_WITHIN 26
#define SH_COUNT 56

__device__ unsigned long long g_acc = 0ull;

__global__ __launch_bounds__(32) void group_loss_fused(
    const float* __restrict__ preds,
    const float* __restrict__ gt,
    float* __restrict__ out)
{
    const int lane = threadIdx.x;
    const int half = lane >> 4;          // 0 -> n0, 1 -> n1
    const int pr   = lane & 15;          // person index within half
    const int n    = blockIdx.x * 2 + half;

    // per-person one-pass moments (pr >= P_NUM lanes carry zeros)
    float sum = 0.0f, sumsq = 0.0f, cnt = 0.0f;
    if (pr < P_NUM) {
        const float2* gp = ((const float2*)gt) + (n * P_NUM + pr) * K_NUM;
        const float* pp = preds + n * (K_NUM * HW * HW);

        float2 g[K_NUM];
        #pragma unroll
        for (int k = 0; k < K_NUM; k++) g[k] = gp[k];   // 17 indep LDG.64

        #pragma unroll
        for (int k = 0; k < K_NUM; k++) {
            // jnp.round = round half to even; rintf matches (RN mode)
            const int x = (int)rintf(g[k].x * 0.25f);
            const int y = (int)rintf(g[k].y * 0.25f);
            const bool valid = (x >= 0) & (x < HW) & (y >= 0) & (y < HW);
            const int xc = min(max(x, 0), HW - 1);
            const int yc = min(max(y, 0), HW - 1);
            float v = pp[(k * HW + yc) * HW + xc];
            v = valid ? v : 0.0f;
            sum   += v;
            sumsq += v * v;
            cnt   += valid ? 1.0f : 0.0f;
        }
    }
    const float safe = fmaxf(cnt, 1.0f);
    const float e = sum / safe;
    // E[(v-e)^2] = E[v^2] - e^2 over valid kps
    float within_p = (cnt > 0.0f) ? fmaxf(sumsq / safe - e * e, 0.0f) : 0.0f;

    const bool pvalid = (pr < P_NUM) && (cnt > 0.0f);
    const unsigned vmask = __ballot_sync(0xffffffffu, pvalid);
    const int nv0 = __popc(vmask & 0xffffu);
    const int nv1 = __popc(vmask >> 16);

    // invalid persons get distinct huge sentinel embeds: any pair with one
    // has |ej - ei| >> 1 -> hinge term exactly 0. (Distinct per lane, so a
    // sentinel-sentinel pair is also >> 1 apart.)
    const float ebc = pvalid ? e : 1.0e7f * (float)(lane + 2);

    // broadcast the 10 person embeds of OWN half
    const int base = half << 4;
    float ej[P_NUM];
    #pragma unroll
    for (int j = 0; j < P_NUM; j++)
        ej[j] = __shfl_sync(0xffffffffu, ebc, base + j);

    float hinge_row = 0.0f;
    if (pvalid) {
        #pragma unroll
        for (int j = 0; j < P_NUM; j++) {
            if (j == pr) continue;
            hinge_row += fmaxf(1.0f - fabsf(ej[j] - e), 0.0f);
        }
    }

    // 4-level butterfly within each 16-lane half (offs < 16 stay in-half)
    #pragma unroll
    for (int off = 8; off > 0; off >>= 1) {
        within_p  += __shfl_xor_sync(0xffffffffu, within_p,  off);
        hinge_row += __shfl_xor_sync(0xffffffffu, hinge_row, off);
    }
    // lane 0 holds n0 sums; fetch n1 sums from lane 16
    const float w1 = __shfl_sync(0xffffffffu, within_p,  16);
    const float h1 = __shfl_sync(0xffffffffu, hinge_row, 16);

    if (lane == 0) {
        const float within0 = within_p * (1.0f / (float)P_NUM);
        const float within1 = w1       * (1.0f / (float)P_NUM);
        const float den0 = (float)(nv0 * (nv0 - 1));
        const float den1 = (float)(nv1 * (nv1 - 1));
        const float across0 = (den0 > 0.0f) ? hinge_row / den0 : 0.0f;
        const float across1 = (den1 > 0.0f) ? h1 / den1 : 0.0f;

        const unsigned long long wq =
            (unsigned long long)__float2uint_rn(within0 * Q_WITHIN) +
            (unsigned long long)__float2uint_rn(within1 * Q_WITHIN);
        const unsigned long long aq =
            (unsigned long long)__float2uint_rn(across0 * Q_ACROSS) +
            (unsigned long long)__float2uint_rn(across1 * Q_ACROSS);
        const unsigned long long contrib =
            (2ull << SH_COUNT) | (wq << SH_WITHIN) | aq;

        const unsigned long long prev = atomicAdd(&g_acc, contrib);

        if ((prev >> SH_COUNT) == (unsigned long long)(N_FLAT - 2)) {
            const unsigned long long tot = prev + contrib;
            const unsigned long long wsum = (tot >> SH_WITHIN) & ((1ull << (SH_COUNT - SH_WITHIN)) - 1ull);
            const unsigned long long asum = tot & ((1ull << SH_WITHIN) - 1ull);
            out[0] = (float)((double)wsum * (1.0 / ((double)Q_WITHIN * N_FLAT)));
            out[1] = (float)((double)asum * (1.0 / ((double)Q_ACROSS * N_FLAT)));
            g_acc = 0ull;   // reset for next graph replay
        }
    }
}

extern "C" void kernel_launch(void* const* d_in, const int* in_sizes, int n_in,
                              void* d_out, int out_size)
{
    const float* preds = (const float*)d_in[0];
    const float* gt    = (const float*)d_in[1];
    float* out = (float*)d_out;
    group_loss_fused<<<N_FLAT / 2, 32>>>(preds, gt, out);
}